// round 6
// baseline (speedup 1.0000x reference)
#include <cuda_runtime.h>
#include <mma.h>
#include <cstdint>

using namespace nvcuda;

#define NB     32
#define NC     512
#define NHEADS 8
#define ND     64
#define NSP    4096   // H*W

// Scratch (no allocations allowed)
__device__ float g_Wr[NC * NC];                 // tf32-rounded W
__device__ float g_W2[(size_t)NB * NC * NC];    // folded W @ blockdiag(A)

__device__ __forceinline__ void st_tf32_4(float* p, float4 v) {
    p[0] = wmma::__float_to_tf32(v.x);
    p[1] = wmma::__float_to_tf32(v.y);
    p[2] = wmma::__float_to_tf32(v.z);
    p[3] = wmma::__float_to_tf32(v.w);
}

__global__ void round_w_kernel(const float* __restrict__ w) {
    int i = blockIdx.x * blockDim.x + threadIdx.x;
    if (i < NC * NC) g_Wr[i] = wmma::__float_to_tf32(w[i]);
}

// ---------------------------------------------------------------------------
// Kernel 1: per (b,h) block.  Gram(L,G) via tf32 WMMA with register prefetch,
// exact fp32 row norms, softmax, then W2 slice = Wr[:,h*64:+64] @ A.
// ---------------------------------------------------------------------------
#define LDA1 36   // ld for 64x32 staging tiles
#define LDS1 68   // ld for 64x64 S / A tile

__global__ __launch_bounds__(256) void attn_kernel(
    const float* __restrict__ localf,
    const float* __restrict__ globalf,
    const float* __restrict__ temp)
{
    __shared__ float sLG[2 * 64 * LDA1];   // sL | sG ; aliased as sS afterwards
    __shared__ float sInv[128];

    float* sL = sLG;
    float* sG = sLG + 64 * LDA1;
    float* sS = sLG;

    const int h = blockIdx.x;
    const int b = blockIdx.y;
    const float* Lp = localf  + (size_t)(b * NC + h * ND) * NSP;
    const float* Gp = globalf + (size_t)(b * NC + h * ND) * NSP;

    const int t    = threadIdx.x;
    const int lane = t & 31;
    const int warp = t >> 5;
    const int srow = t >> 2;         // 0..63
    const int scol = (t & 3) * 8;    // 0,8,16,24

    const int m0 = (warp & 1) * 32;
    const int n0 = (warp >> 1) * 16;

    wmma::fragment<wmma::accumulator, 16, 16, 8, float> acc0, acc1;
    wmma::fill_fragment(acc0, 0.0f);
    wmma::fill_fragment(acc1, 0.0f);

    float sqL = 0.f, sqG = 0.f;

    const float* lrow0 = Lp + (size_t)srow * NSP + scol;
    const float* grow0 = Gp + (size_t)srow * NSP + scol;

    // prefetch chunk 0
    float4 l0 = ((const float4*)lrow0)[0];
    float4 l1 = ((const float4*)lrow0)[1];
    float4 g0 = ((const float4*)grow0)[0];
    float4 g1 = ((const float4*)grow0)[1];

    for (int k0 = 0; k0 < NSP; k0 += 32) {
        sqL += l0.x*l0.x + l0.y*l0.y + l0.z*l0.z + l0.w*l0.w
             + l1.x*l1.x + l1.y*l1.y + l1.z*l1.z + l1.w*l1.w;
        sqG += g0.x*g0.x + g0.y*g0.y + g0.z*g0.z + g0.w*g0.w
             + g1.x*g1.x + g1.y*g1.y + g1.z*g1.z + g1.w*g1.w;

        float* dl = sL + srow * LDA1 + scol;
        float* dg = sG + srow * LDA1 + scol;
        st_tf32_4(dl,     l0);
        st_tf32_4(dl + 4, l1);
        st_tf32_4(dg,     g0);
        st_tf32_4(dg + 4, g1);
        __syncthreads();

        // prefetch next chunk while tensor pipe works on this one
        if (k0 + 32 < NSP) {
            const float* ln = lrow0 + k0 + 32;
            const float* gn = grow0 + k0 + 32;
            l0 = ((const float4*)ln)[0];
            l1 = ((const float4*)ln)[1];
            g0 = ((const float4*)gn)[0];
            g1 = ((const float4*)gn)[1];
        }

        #pragma unroll
        for (int kk = 0; kk < 32; kk += 8) {
            wmma::fragment<wmma::matrix_b, 16, 16, 8, wmma::precision::tf32, wmma::col_major> bf;
            wmma::load_matrix_sync(bf, sG + n0 * LDA1 + kk, LDA1);
            wmma::fragment<wmma::matrix_a, 16, 16, 8, wmma::precision::tf32, wmma::row_major> af;
            wmma::load_matrix_sync(af, sL + m0 * LDA1 + kk, LDA1);
            wmma::mma_sync(acc0, af, bf, acc0);
            wmma::load_matrix_sync(af, sL + (m0 + 16) * LDA1 + kk, LDA1);
            wmma::mma_sync(acc1, af, bf, acc1);
        }
        __syncthreads();
    }

    sqL += __shfl_xor_sync(0xffffffffu, sqL, 1);
    sqL += __shfl_xor_sync(0xffffffffu, sqL, 2);
    sqG += __shfl_xor_sync(0xffffffffu, sqG, 1);
    sqG += __shfl_xor_sync(0xffffffffu, sqG, 2);
    if ((t & 3) == 0) {
        sInv[srow]      = 1.f / fmaxf(sqrtf(sqL), 1e-12f);
        sInv[64 + srow] = 1.f / fmaxf(sqrtf(sqG), 1e-12f);
    }

    wmma::store_matrix_sync(sS + m0 * LDS1 + n0, acc0, LDS1, wmma::mem_row_major);
    wmma::store_matrix_sync(sS + (m0 + 16) * LDS1 + n0, acc1, LDS1, wmma::mem_row_major);
    __syncthreads();

    const float tval = temp[h];
    for (int rr = warp * 8; rr < warp * 8 + 8; ++rr) {
        float il = sInv[rr] * tval;
        float x1 = sS[rr * LDS1 + lane]      * il * sInv[64 + lane];
        float x2 = sS[rr * LDS1 + 32 + lane] * il * sInv[96 + lane];
        float mx = fmaxf(x1, x2);
        #pragma unroll
        for (int o = 16; o > 0; o >>= 1)
            mx = fmaxf(mx, __shfl_xor_sync(0xffffffffu, mx, o));
        float e1 = expf(x1 - mx);
        float e2 = expf(x2 - mx);
        float s = e1 + e2;
        #pragma unroll
        for (int o = 16; o > 0; o >>= 1)
            s += __shfl_xor_sync(0xffffffffu, s, o);
        float is = 1.f / s;
        sS[rr * LDS1 + lane]      = wmma::__float_to_tf32(e1 * is);
        sS[rr * LDS1 + 32 + lane] = wmma::__float_to_tf32(e2 * is);
    }
    __syncthreads();

    // W2 slice: [512 x 64] = Wr[:, h*64:+64] @ A
    const int o0 = warp * 64;
    wmma::fragment<wmma::accumulator, 16, 16, 8, float> wacc[4][4];
    #pragma unroll
    for (int i = 0; i < 4; ++i)
        #pragma unroll
        for (int j = 0; j < 4; ++j)
            wmma::fill_fragment(wacc[i][j], 0.0f);

    #pragma unroll
    for (int kk = 0; kk < 64; kk += 8) {
        wmma::fragment<wmma::matrix_b, 16, 16, 8, wmma::precision::tf32, wmma::row_major> bf[4];
        #pragma unroll
        for (int j = 0; j < 4; ++j)
            wmma::load_matrix_sync(bf[j], sS + kk * LDS1 + j * 16, LDS1);
        #pragma unroll
        for (int i = 0; i < 4; ++i) {
            wmma::fragment<wmma::matrix_a, 16, 16, 8, wmma::precision::tf32, wmma::row_major> af;
            wmma::load_matrix_sync(af, g_Wr + (size_t)(o0 + i * 16) * NC + h * ND + kk, NC);
            #pragma unroll
            for (int j = 0; j < 4; ++j)
                wmma::mma_sync(wacc[i][j], af, bf[j], wacc[i][j]);
        }
    }
    float* w2p = g_W2 + (size_t)b * NC * NC;
    #pragma unroll
    for (int i = 0; i < 4; ++i)
        #pragma unroll
        for (int j = 0; j < 4; ++j)
            wmma::store_matrix_sync(w2p + (size_t)(o0 + i * 16) * NC + h * ND + j * 16,
                                    wacc[i][j], NC, wmma::mem_row_major);
}

// ---------------------------------------------------------------------------
// Kernel 3: out[b] = W2[b] (512x512) @ G[b] (512x4096), tf32 WMMA.
// 128x128 CTA tile, KT=16, double-buffered SMEM + register prefetch,
// ONE __syncthreads per K-chunk.  B consumed in G's native [K][N] layout.
// ---------------------------------------------------------------------------
#define KT3   16
#define LDA3  20    // 128 x 16 A tile, padded
#define LDB3  132   // 16 x 128 B tile, padded
#define ASZ3  (128 * LDA3)
#define BSZ3  (KT3 * LDB3)

__global__ __launch_bounds__(256) void proj_kernel(
    const float* __restrict__ globalf, float* __restrict__ outp)
{
    __shared__ float sA[2 * ASZ3];
    __shared__ float sB[2 * BSZ3];

    const int b  = blockIdx.z;
    const int o0 = blockIdx.y * 128;
    const int n0 = blockIdx.x * 128;
    const float* Ap = g_W2 + (size_t)b * NC * NC + (size_t)o0 * NC;   // [128][512]
    const float* Bp = globalf + (size_t)b * NC * NSP + n0;            // [512][4096] col window

    const int t    = threadIdx.x;
    const int warp = t >> 5;
    const int mw = (warp >> 2) * 64;
    const int nw = (warp & 3) * 32;

    // A chunk [128 m][16 k]: 2048 floats / 256 thr = 8 floats each
    const int arow = t >> 1, acol = (t & 1) * 8;
    // B chunk [16 k][128 n]: 2048 floats
    const int brow = t >> 4, bcol = (t & 15) * 8;

    wmma::fragment<wmma::accumulator, 16, 16, 8, float> acc[4][2];
    #pragma unroll
    for (int i = 0; i < 4; ++i)
        #pragma unroll
        for (int j = 0; j < 2; ++j)
            wmma::fill_fragment(acc[i][j], 0.0f);

    const float* agBase = Ap + (size_t)arow * NC + acol;
    const float* bgBase = Bp + (size_t)brow * NSP + bcol;

    // prefetch chunk 0
    float4 av0 = ((const float4*)agBase)[0];
    float4 av1 = ((const float4*)agBase)[1];
    float4 bv0 = ((const float4*)bgBase)[0];
    float4 bv1 = ((const float4*)bgBase)[1];

    #pragma unroll 4
    for (int kc = 0; kc < NC / KT3; ++kc) {
        float* sa = sA + (kc & 1) * ASZ3;
        float* sb = sB + (kc & 1) * BSZ3;

        st_tf32_4(sa + arow * LDA3 + acol,     av0);
        st_tf32_4(sa + arow * LDA3 + acol + 4, av1);
        st_tf32_4(sb + brow * LDB3 + bcol,     bv0);
        st_tf32_4(sb + brow * LDB3 + bcol + 4, bv1);
        __syncthreads();

        if (kc + 1 < NC / KT3) {
            const float* ag = agBase + (kc + 1) * KT3;
            const float* bg = bgBase + (size_t)(kc + 1) * KT3 * NSP;
            av0 = ((const float4*)ag)[0];
            av1 = ((const float4*)ag)[1];
            bv0 = ((const float4*)bg)[0];
            bv1 = ((const float4*)bg)[1];
        }

        #pragma unroll
        for (int kk = 0; kk < KT3; kk += 8) {
            wmma::fragment<wmma::matrix_b, 16, 16, 8, wmma::precision::tf32, wmma::row_major> bf[2];
            #pragma unroll
            for (int j = 0; j < 2; ++j)
                wmma::load_matrix_sync(bf[j], sb + kk * LDB3 + nw + j * 16, LDB3);
            #pragma unroll
            for (int i = 0; i < 4; ++i) {
                wmma::fragment<wmma::matrix_a, 16, 16, 8, wmma::precision::tf32, wmma::row_major> af;
                wmma::load_matrix_sync(af, sa + (mw + i * 16) * LDA3 + kk, LDA3);
                #pragma unroll
                for (int j = 0; j < 2; ++j)
                    wmma::mma_sync(acc[i][j], af, bf[j], acc[i][j]);
            }
        }
        // no second barrier: next iteration writes the other buffer, and its
        // top-of-loop barrier orders those stores after everyone's MMA here.
    }

    #pragma unroll
    for (int i = 0; i < 4; ++i)
        #pragma unroll
        for (int j = 0; j < 2; ++j)
            wmma::store_matrix_sync(
                outp + (size_t)(b * NC + o0 + mw + i * 16) * NSP + n0 + nw + j * 16,
                acc[i][j], NSP, wmma::mem_row_major);
}

extern "C" void kernel_launch(void* const* d_in, const int* in_sizes, int n_in,
                              void* d_out, int out_size) {
    (void)in_sizes; (void)n_in; (void)out_size;
    const float* localf  = (const float*)d_in[0];
    const float* globalf = (const float*)d_in[1];
    const float* temp    = (const float*)d_in[2];
    const float* projw   = (const float*)d_in[3];
    float* outp = (float*)d_out;

    round_w_kernel<<<(NC * NC + 511) / 512, 512>>>(projw);

    dim3 g1(NHEADS, NB);
    attn_kernel<<<g1, 256>>>(localf, globalf, temp);

    dim3 g3(NSP / 128, NC / 128, NB);
    proj_kernel<<<g3, 256>>>(globalf, outp);
}

// round 7
// speedup vs baseline: 1.2626x; 1.2626x over previous
#include <cuda_runtime.h>
#include <mma.h>
#include <cstdint>

using namespace nvcuda;

#define NB     32
#define NC     512
#define NHEADS 8
#define ND     64
#define NSP    4096   // H*W

// Scratch (no allocations allowed): folded W @ blockdiag(A), raw f32
__device__ float g_W2[(size_t)NB * NC * NC];

// ---------------------------------------------------------------------------
// helpers
// ---------------------------------------------------------------------------
__device__ __forceinline__ uint32_t smem_u32(const void* p) {
    uint32_t a;
    asm("{ .reg .u64 t; cvta.to.shared.u64 t, %1; cvt.u32.u64 %0, t; }" : "=r"(a) : "l"(p));
    return a;
}
__device__ __forceinline__ void cp16(void* dst_smem, const void* src) {
    asm volatile("cp.async.cg.shared.global [%0], [%1], 16;"
                 :: "r"(smem_u32(dst_smem)), "l"(src));
}
#define CP_COMMIT() asm volatile("cp.async.commit_group;" ::: "memory")
#define CP_WAIT(n)  asm volatile("cp.async.wait_group %0;" :: "n"(n) : "memory")

template <class Frag>
__device__ __forceinline__ void round_frag(Frag& f) {
    #pragma unroll
    for (int e = 0; e < f.num_elements; ++e)
        f.x[e] = wmma::__float_to_tf32(f.x[e]);
}

// ---------------------------------------------------------------------------
// Kernel 1: per (b,h).  Phase A: 2-stage cp.async pipeline over 64x32 chunks;
// exact fp32 sumsq read back from raw SMEM; Gram via tf32 WMMA with
// in-register rounding.  Phase B: softmax.  Phase C: W2 slice = W[:,h*64:+64]@A
// with W fragments loaded straight from global and rounded in-register.
// ---------------------------------------------------------------------------
#define LDA1 36
#define STG1 (2 * 64 * LDA1)   // one stage: L(64x36) + G(64x36) = 4608 floats
#define LDS1 68

__global__ __launch_bounds__(256) void attn_kernel(
    const float* __restrict__ localf,
    const float* __restrict__ globalf,
    const float* __restrict__ temp,
    const float* __restrict__ projw)
{
    __shared__ float sMem[2 * STG1];    // 2 stages; aliased as sS afterwards
    __shared__ float sInv[128];
    float* sS = sMem;                   // 64*68 = 4352 floats

    const int h = blockIdx.x;
    const int b = blockIdx.y;
    const float* Lp = localf  + (size_t)(b * NC + h * ND) * NSP;
    const float* Gp = globalf + (size_t)(b * NC + h * ND) * NSP;

    const int t    = threadIdx.x;
    const int lane = t & 31;
    const int warp = t >> 5;
    const int srow = t >> 2;         // 0..63
    const int scol = (t & 3) * 8;    // 0,8,16,24

    const int m0 = (warp & 1) * 32;
    const int n0 = (warp >> 1) * 16;

    wmma::fragment<wmma::accumulator, 16, 16, 8, float> acc0, acc1;
    wmma::fill_fragment(acc0, 0.0f);
    wmma::fill_fragment(acc1, 0.0f);

    float sqL = 0.f, sqG = 0.f;

    const float* lsrc = Lp + (size_t)srow * NSP + scol;
    const float* gsrc = Gp + (size_t)srow * NSP + scol;
    float* ldst = sMem + srow * LDA1 + scol;
    float* gdst = sMem + 64 * LDA1 + srow * LDA1 + scol;

    // prologue: issue chunks 0,1
    #pragma unroll
    for (int kc = 0; kc < 2; ++kc) {
        float* dl = ldst + kc * STG1;
        float* dg = gdst + kc * STG1;
        cp16(dl, lsrc + kc * 32); cp16(dl + 4, lsrc + kc * 32 + 4);
        cp16(dg, gsrc + kc * 32); cp16(dg + 4, gsrc + kc * 32 + 4);
        CP_COMMIT();
    }

    for (int kc = 0; kc < 128; ++kc) {
        CP_WAIT(1);
        __syncthreads();

        float* stg = sMem + (kc & 1) * STG1;
        float* sL = stg;
        float* sG = stg + 64 * LDA1;

        // exact fp32 sum-of-squares from raw staged data
        {
            const float4* lp4 = (const float4*)(sL + srow * LDA1 + scol);
            const float4* gp4 = (const float4*)(sG + srow * LDA1 + scol);
            float4 l0 = lp4[0], l1 = lp4[1], g0 = gp4[0], g1 = gp4[1];
            sqL += l0.x*l0.x + l0.y*l0.y + l0.z*l0.z + l0.w*l0.w
                 + l1.x*l1.x + l1.y*l1.y + l1.z*l1.z + l1.w*l1.w;
            sqG += g0.x*g0.x + g0.y*g0.y + g0.z*g0.z + g0.w*g0.w
                 + g1.x*g1.x + g1.y*g1.y + g1.z*g1.z + g1.w*g1.w;
        }

        #pragma unroll
        for (int kk = 0; kk < 32; kk += 8) {
            wmma::fragment<wmma::matrix_b, 16, 16, 8, wmma::precision::tf32, wmma::col_major> bf;
            wmma::load_matrix_sync(bf, sG + n0 * LDA1 + kk, LDA1);
            round_frag(bf);
            wmma::fragment<wmma::matrix_a, 16, 16, 8, wmma::precision::tf32, wmma::row_major> af;
            wmma::load_matrix_sync(af, sL + m0 * LDA1 + kk, LDA1);
            round_frag(af);
            wmma::mma_sync(acc0, af, bf, acc0);
            wmma::load_matrix_sync(af, sL + (m0 + 16) * LDA1 + kk, LDA1);
            round_frag(af);
            wmma::mma_sync(acc1, af, bf, acc1);
        }
        __syncthreads();

        if (kc + 2 < 128) {
            const int kn = kc + 2;
            float* dl = ldst + (kn & 1) * STG1;
            float* dg = gdst + (kn & 1) * STG1;
            cp16(dl, lsrc + kn * 32); cp16(dl + 4, lsrc + kn * 32 + 4);
            cp16(dg, gsrc + kn * 32); cp16(dg + 4, gsrc + kn * 32 + 4);
            CP_COMMIT();
        } else {
            CP_COMMIT();   // keep group count advancing for CP_WAIT(1)
        }
    }

    sqL += __shfl_xor_sync(0xffffffffu, sqL, 1);
    sqL += __shfl_xor_sync(0xffffffffu, sqL, 2);
    sqG += __shfl_xor_sync(0xffffffffu, sqG, 1);
    sqG += __shfl_xor_sync(0xffffffffu, sqG, 2);
    if ((t & 3) == 0) {
        sInv[srow]      = 1.f / fmaxf(sqrtf(sqL), 1e-12f);
        sInv[64 + srow] = 1.f / fmaxf(sqrtf(sqG), 1e-12f);
    }

    wmma::store_matrix_sync(sS + m0 * LDS1 + n0, acc0, LDS1, wmma::mem_row_major);
    wmma::store_matrix_sync(sS + (m0 + 16) * LDS1 + n0, acc1, LDS1, wmma::mem_row_major);
    __syncthreads();

    const float tval = temp[h];
    for (int rr = warp * 8; rr < warp * 8 + 8; ++rr) {
        float il = sInv[rr] * tval;
        float x1 = sS[rr * LDS1 + lane]      * il * sInv[64 + lane];
        float x2 = sS[rr * LDS1 + 32 + lane] * il * sInv[96 + lane];
        float mx = fmaxf(x1, x2);
        #pragma unroll
        for (int o = 16; o > 0; o >>= 1)
            mx = fmaxf(mx, __shfl_xor_sync(0xffffffffu, mx, o));
        float e1 = expf(x1 - mx);
        float e2 = expf(x2 - mx);
        float s = e1 + e2;
        #pragma unroll
        for (int o = 16; o > 0; o >>= 1)
            s += __shfl_xor_sync(0xffffffffu, s, o);
        float is = 1.f / s;
        sS[rr * LDS1 + lane]      = wmma::__float_to_tf32(e1 * is);
        sS[rr * LDS1 + 32 + lane] = wmma::__float_to_tf32(e2 * is);
    }
    __syncthreads();

    // W2 slice: [512 x 64] = W[:, h*64:+64] @ A  (W straight from global, rounded)
    const int o0 = warp * 64;
    wmma::fragment<wmma::accumulator, 16, 16, 8, float> wacc[4][4];
    #pragma unroll
    for (int i = 0; i < 4; ++i)
        #pragma unroll
        for (int j = 0; j < 4; ++j)
            wmma::fill_fragment(wacc[i][j], 0.0f);

    #pragma unroll
    for (int kk = 0; kk < 64; kk += 8) {
        wmma::fragment<wmma::matrix_b, 16, 16, 8, wmma::precision::tf32, wmma::row_major> bf[4];
        #pragma unroll
        for (int j = 0; j < 4; ++j)
            wmma::load_matrix_sync(bf[j], sS + kk * LDS1 + j * 16, LDS1);
        #pragma unroll
        for (int i = 0; i < 4; ++i) {
            wmma::fragment<wmma::matrix_a, 16, 16, 8, wmma::precision::tf32, wmma::row_major> af;
            wmma::load_matrix_sync(af, projw + (size_t)(o0 + i * 16) * NC + h * ND + kk, NC);
            round_frag(af);
            #pragma unroll
            for (int j = 0; j < 4; ++j)
                wmma::mma_sync(wacc[i][j], af, bf[j], wacc[i][j]);
        }
    }
    float* w2p = g_W2 + (size_t)b * NC * NC;
    #pragma unroll
    for (int i = 0; i < 4; ++i)
        #pragma unroll
        for (int j = 0; j < 4; ++j)
            wmma::store_matrix_sync(w2p + (size_t)(o0 + i * 16) * NC + h * ND + j * 16,
                                    wacc[i][j], NC, wmma::mem_row_major);
}

// ---------------------------------------------------------------------------
// Kernel 2: out[b] = W2[b] (512x512) @ G[b] (512x4096), tf32 WMMA.
// CTA tile 128(m) x 256(n), KT=32, 3-stage cp.async pipeline, operands kept
// raw in SMEM and rounded in-register per fragment.  8 warps, warp tile 64x64.
// ---------------------------------------------------------------------------
#define KTP  32
#define LDAP 36                  // 128 x 32 A tile, padded (144 B rows, 16B-mult)
#define LDBP 260                 // 32 x 256 B tile, padded (1040 B rows, 16B-mult)
#define ASZP (128 * LDAP)        // 4608 floats
#define BSZP (KTP * LDBP)        // 8320 floats
#define STGP (ASZP + BSZP)       // 12928 floats = 51712 B per stage
#define NSTG 3

__global__ __launch_bounds__(256) void proj_kernel(
    const float* __restrict__ globalf, float* __restrict__ outp)
{
    extern __shared__ float psm[];   // NSTG * STGP floats

    const int b  = blockIdx.z;
    const int o0 = blockIdx.y * 128;
    const int n0 = blockIdx.x * 256;
    const float* Ap = g_W2 + (size_t)b * NC * NC + (size_t)o0 * NC;   // [128][512]
    const float* Bp = globalf + (size_t)b * NC * NSP + n0;            // [512][col window 256]

    const int t    = threadIdx.x;
    const int warp = t >> 5;
    const int mw = (warp >> 2) * 64;   // 0 or 64
    const int nw = (warp & 3) * 64;    // 0,64,128,192

    // cp.async mappings
    const int ar = t >> 1,  aq = (t & 1) * 16;   // A: 128 rows x 32 k, 16 floats/thr
    const int br = t >> 3,  bq = (t & 7) * 32;   // B: 32 rows x 256 n, 32 floats/thr

    wmma::fragment<wmma::accumulator, 16, 16, 8, float> acc[4][4];
    #pragma unroll
    for (int i = 0; i < 4; ++i)
        #pragma unroll
        for (int j = 0; j < 4; ++j)
            wmma::fill_fragment(acc[i][j], 0.0f);

    const float* agBase = Ap + (size_t)ar * NC + aq;
    const float* bgBase = Bp + (size_t)br * NSP + bq;

    // prologue: fill 3 stages
    #pragma unroll
    for (int kc = 0; kc < NSTG; ++kc) {
        float* sa = psm + kc * STGP;
        float* sb = sa + ASZP;
        const float* ag = agBase + kc * KTP;
        const float* bg = bgBase + (size_t)kc * KTP * NSP;
        #pragma unroll
        for (int j = 0; j < 4; ++j)
            cp16(sa + ar * LDAP + aq + j * 4, ag + j * 4);
        #pragma unroll
        for (int j = 0; j < 8; ++j)
            cp16(sb + br * LDBP + bq + j * 4, bg + j * 4);
        CP_COMMIT();
    }

    for (int kc = 0; kc < NC / KTP; ++kc) {
        CP_WAIT(2);
        __syncthreads();

        float* sa = psm + (kc % NSTG) * STGP;
        float* sb = sa + ASZP;

        #pragma unroll
        for (int kk = 0; kk < KTP; kk += 8) {
            wmma::fragment<wmma::matrix_b, 16, 16, 8, wmma::precision::tf32, wmma::row_major> bf[4];
            #pragma unroll
            for (int j = 0; j < 4; ++j) {
                wmma::load_matrix_sync(bf[j], sb + kk * LDBP + nw + j * 16, LDBP);
                round_frag(bf[j]);
            }
            #pragma unroll
            for (int i = 0; i < 4; ++i) {
                wmma::fragment<wmma::matrix_a, 16, 16, 8, wmma::precision::tf32, wmma::row_major> af;
                wmma::load_matrix_sync(af, sa + (mw + i * 16) * LDAP + kk, LDAP);
                round_frag(af);
                #pragma unroll
                for (int j = 0; j < 4; ++j)
                    wmma::mma_sync(acc[i][j], af, bf[j], acc[i][j]);
            }
        }
        __syncthreads();

        const int kn = kc + NSTG;
        if (kn < NC / KTP) {
            float* na = psm + (kn % NSTG) * STGP;
            float* nb = na + ASZP;
            const float* ag = agBase + kn * KTP;
            const float* bg = bgBase + (size_t)kn * KTP * NSP;
            #pragma unroll
            for (int j = 0; j < 4; ++j)
                cp16(na + ar * LDAP + aq + j * 4, ag + j * 4);
            #pragma unroll
            for (int j = 0; j < 8; ++j)
                cp16(nb + br * LDBP + bq + j * 4, bg + j * 4);
        }
        CP_COMMIT();
    }

    #pragma unroll
    for (int i = 0; i < 4; ++i)
        #pragma unroll
        for (int j = 0; j < 4; ++j)
            wmma::store_matrix_sync(
                outp + (size_t)(b * NC + o0 + mw + i * 16) * NSP + n0 + nw + j * 16,
                acc[i][j], NSP, wmma::mem_row_major);
}

extern "C" void kernel_launch(void* const* d_in, const int* in_sizes, int n_in,
                              void* d_out, int out_size) {
    (void)in_sizes; (void)n_in; (void)out_size;
    const float* localf  = (const float*)d_in[0];
    const float* globalf = (const float*)d_in[1];
    const float* temp    = (const float*)d_in[2];
    const float* projw   = (const float*)d_in[3];
    float* outp = (float*)d_out;

    dim3 g1(NHEADS, NB);
    attn_kernel<<<g1, 256>>>(localf, globalf, temp, projw);

    static_assert(NSTG * STGP * sizeof(float) <= 160 * 1024, "smem budget");
    cudaFuncSetAttribute(proj_kernel, cudaFuncAttributeMaxDynamicSharedMemorySize,
                         NSTG * STGP * (int)sizeof(float));
    dim3 g3(NSP / 256, NC / 128, NB);
    proj_kernel<<<g3, 256, NSTG * STGP * sizeof(float)>>>(globalf, outp);
}